// round 10
// baseline (speedup 1.0000x reference)
#include <cuda_runtime.h>
#include <mma.h>
#include <cstdint>
#include <cstddef>

using namespace nvcuda;

#define Bv   2
#define Sv   2048
#define Hv   2048
#define NHv  16
#define HDv  128
#define BSv  256
#define Mtot (Bv * Sv)
#define ATT_SCALE 0.08838834764831843f  // 1/sqrt(128)

// ---------------- scratch (__device__ globals, allocation-free rule) -------
__device__ float g_q[(size_t)Mtot * Hv];
__device__ float g_k[(size_t)Mtot * Hv];
__device__ float g_v[(size_t)Mtot * Hv];
__device__ float g_o[(size_t)Mtot * Hv];
__device__ float g_xr[(size_t)Mtot * Hv];
__device__ float g_wq[(size_t)Hv * Hv];
__device__ float g_wk[(size_t)Hv * Hv];
__device__ float g_wv[(size_t)Hv * Hv];
__device__ float g_wo[(size_t)Hv * Hv];

// ---------------- helpers ---------------------------------------------------
__device__ __forceinline__ float to_tf32(float x) {
    float y;
    asm("cvt.rna.tf32.f32 %0, %1;" : "=f"(y) : "f"(x));
    return y;
}

__device__ __forceinline__ uint32_t smem_u32(const void* p) {
    uint32_t a;
    asm("{ .reg .u64 t; cvta.to.shared.u64 t, %1; cvt.u32.u64 %0, t; }" : "=r"(a) : "l"(p));
    return a;
}

__device__ __forceinline__ void cp_async16(uint32_t saddr, const void* gptr) {
    asm volatile("cp.async.cg.shared.global [%0], [%1], 16;" :: "r"(saddr), "l"(gptr));
}
#define CP_COMMIT() asm volatile("cp.async.commit_group;")
#define CP_WAIT(n)  asm volatile("cp.async.wait_group %0;" :: "n"(n))

// ---------------- merged rounding pre-pass (one launch) ---------------------
#define NX4 (Mtot * Hv / 4)   // 2,097,152
#define NW4 (Hv * Hv / 4)     // 1,048,576

__global__ void __launch_bounds__(256) round_all_k(
    const float4* __restrict__ X,  const float4* __restrict__ Wq,
    const float4* __restrict__ Wk, const float4* __restrict__ Wv,
    const float4* __restrict__ Wo)
{
    int i = blockIdx.x * 256 + threadIdx.x;
    const float4* s; float4* d; int off;
    if (i < NX4)               { s = X;  d = (float4*)g_xr; off = i; }
    else if (i < NX4 + NW4)    { s = Wq; d = (float4*)g_wq; off = i - NX4; }
    else if (i < NX4 + 2*NW4)  { s = Wk; d = (float4*)g_wk; off = i - NX4 - NW4; }
    else if (i < NX4 + 3*NW4)  { s = Wv; d = (float4*)g_wv; off = i - NX4 - 2*NW4; }
    else                       { s = Wo; d = (float4*)g_wo; off = i - NX4 - 3*NW4; }
    float4 v = s[off];
    v.x = to_tf32(v.x); v.y = to_tf32(v.y);
    v.z = to_tf32(v.z); v.w = to_tf32(v.w);
    d[off] = v;
}

// ===========================================================================
// Pipelined tf32 wmma GEMM — EXACT R4 configuration (best measured):
// CTA tile 256x128x32, 8 warps (4x2) with 64x64 warp tiles, 4-stage cp.async,
// 1 CTA/SM, separate launch per GEMM. do_round=1 -> epilogue tf32-rounds C.
// ===========================================================================
#define BM 256
#define BN 128
#define BK 32
#define STR 36                       // 32 + 4 pad floats; 144B rows (16B-aligned)
#define NSTG 4
#define A_FLTS (BM * STR)            // 9216
#define B_FLTS (BN * STR)            // 4608
#define STAGE_FLTS (A_FLTS + B_FLTS) // 13824
#define GEMM_SMEM (NSTG * STAGE_FLTS * 4)   // 221184 B -> 1 CTA/SM

__device__ __forceinline__ void stage_load(
    float* stg, const float* __restrict__ Ag, const float* __restrict__ Bg,
    int K, int tid)
{
#pragma unroll
    for (int i = 0; i < 8; i++) {      // A: 256 rows x 8 x 16B
        int id = tid + i * 256;
        int r = id >> 3, c = id & 7;
        cp_async16(smem_u32(stg + r * STR + c * 4), Ag + (size_t)r * K + c * 4);
    }
#pragma unroll
    for (int i = 0; i < 4; i++) {      // B: 128 rows x 8 x 16B
        int id = tid + i * 256;
        int r = id >> 3, c = id & 7;
        cp_async16(smem_u32(stg + A_FLTS + r * STR + c * 4), Bg + (size_t)r * K + c * 4);
    }
}

__global__ void __launch_bounds__(256, 1) gemm_pipe(
    const float* __restrict__ A, const float* __restrict__ Bw,
    float* __restrict__ C, int M, int N, int K, int do_round)
{
    extern __shared__ __align__(16) float sm[];

    const int tid = threadIdx.x;
    const int wid = tid >> 5;
    const int m0 = blockIdx.y * BM;
    const int n0 = blockIdx.x * BN;
    const int wm = wid & 3;    // 4 warp rows x 64 m
    const int wn = wid >> 2;   // 2 warp cols x 64 n

    const float* Abase = A + (size_t)m0 * K;
    const float* Bbase = Bw + (size_t)n0 * K;
    const int KT = K / BK;

    wmma::fragment<wmma::accumulator, 16, 16, 8, float> acc[4][4];
#pragma unroll
    for (int i = 0; i < 4; i++)
#pragma unroll
        for (int j = 0; j < 4; j++) wmma::fill_fragment(acc[i][j], 0.0f);

#pragma unroll
    for (int t = 0; t < NSTG - 1; t++) {
        stage_load(sm + t * STAGE_FLTS, Abase + t * BK, Bbase + t * BK, K, tid);
        CP_COMMIT();
    }

    for (int kt = 0; kt < KT; kt++) {
        CP_WAIT(NSTG - 2);          // k-tile kt resident
        __syncthreads();            // also fences reads of the stage refilled below

        int tn = kt + NSTG - 1;
        if (tn < KT)
            stage_load(sm + (tn % NSTG) * STAGE_FLTS, Abase + (size_t)tn * BK,
                       Bbase + (size_t)tn * BK, K, tid);
        CP_COMMIT();

        const float* sA = sm + (kt % NSTG) * STAGE_FLTS;
        const float* sB = sA + A_FLTS;

#pragma unroll
        for (int kk = 0; kk < 4; kk++) {
            wmma::fragment<wmma::matrix_a, 16, 16, 8, wmma::precision::tf32, wmma::row_major> af[4];
            wmma::fragment<wmma::matrix_b, 16, 16, 8, wmma::precision::tf32, wmma::col_major> bf[4];
#pragma unroll
            for (int i = 0; i < 4; i++)
                wmma::load_matrix_sync(af[i], sA + (wm * 64 + i * 16) * STR + kk * 8, STR);
#pragma unroll
            for (int j = 0; j < 4; j++)
                wmma::load_matrix_sync(bf[j], sB + (wn * 64 + j * 16) * STR + kk * 8, STR);
#pragma unroll
            for (int j = 0; j < 4; j++)
#pragma unroll
                for (int i = 0; i < 4; i++)
                    wmma::mma_sync(acc[i][j], af[i], bf[j], acc[i][j]);
        }
    }

#pragma unroll
    for (int i = 0; i < 4; i++)
#pragma unroll
        for (int j = 0; j < 4; j++) {
            if (do_round) {
#pragma unroll
                for (int t = 0; t < acc[i][j].num_elements; t++)
                    acc[i][j].x[t] = to_tf32(acc[i][j].x[t]);
            }
            wmma::store_matrix_sync(
                C + (size_t)(m0 + wm * 64 + i * 16) * N + n0 + wn * 64 + j * 16,
                acc[i][j], N, wmma::mem_row_major);
        }
}

// ===========================================================================
// Attention — R4 static-loop structure with two local improvements:
//  (1) softmax without the max pass (shift-invariant; scores are O(+-6))
//  (2) Q held in registers as 16 matrix_a fragments per warp, loaded once.
// K/V subtiles double-buffered via cp.async, one subtile ahead.
// ===========================================================================
#define QT  64
#define AST 132   // 128 + 4 pad
#define SST 260   // 256 + 4 pad

__global__ void __launch_bounds__(256) attn_kernel()
{
    extern __shared__ __align__(16) float sm[];
    float* shQ  = sm;                          // [64][AST]
    float* shKV[2] = { shQ + QT * AST, shQ + 2 * QT * AST };
    float* shS  = shQ + 3 * QT * AST;          // [64][SST]

    const int tid = threadIdx.x;
    const int wid = tid >> 5;
    const int qt = blockIdx.x;
    const int h  = blockIdx.y;
    const int b  = blockIdx.z;
    const int qbase = qt * QT;
    const int bi = qbase >> 8;

    const float* Qp    = g_q + ((size_t)b * Sv + qbase) * Hv + h * HDv;
    const float* Kbase = g_k + ((size_t)b * Sv) * Hv + h * HDv;
    const float* Vbase = g_v + ((size_t)b * Sv) * Hv + h * HDv;

    auto load64 = [&](float* dst, const float* src) {
#pragma unroll
        for (int i = 0; i < 8; i++) {
            int id = tid + i * 256;
            int r = id >> 5, c4 = id & 31;
            cp_async16(smem_u32(dst + r * AST + c4 * 4), src + (size_t)r * Hv + c4 * 4);
        }
    };

    const int wms = wid & 3,  wns = wid >> 2;   // S phase: 16 rows x 32 cols
    const int wmo = wid & 1,  wno = wid >> 1;   // O phase: 32 rows x 32 cols

    // ---- Q tile -> smem -> register fragments (once) ----
    load64(shQ, Qp);
    CP_COMMIT();
    CP_WAIT(0);
    __syncthreads();

    wmma::fragment<wmma::matrix_a, 16, 16, 8, wmma::precision::tf32, wmma::row_major> qf[16];
#pragma unroll
    for (int k = 0; k < 16; k++)
        wmma::load_matrix_sync(qf[k], shQ + (wms * 16) * AST + k * 8, AST);

    load64(shKV[0], Kbase);   // K(jb=0, sub=0)
    CP_COMMIT();

    wmma::fragment<wmma::accumulator, 16, 16, 8, float> acc_o[2][2];
#pragma unroll
    for (int i = 0; i < 2; i++)
#pragma unroll
        for (int j = 0; j < 2; j++) wmma::fill_fragment(acc_o[i][j], 0.0f);

    const int row  = tid >> 2;
    const int part = tid & 3;
    const int qoff = (qbase & 255) + row;

    for (int jb = 0; jb <= bi; jb++) {
        const float* Kj = Kbase + (size_t)jb * BSv * Hv;
        const float* Vj = Vbase + (size_t)jb * BSv * Hv;

        // ---- S phase: 4 subtiles of 64 keys ----
#pragma unroll
        for (int s = 0; s < 4; s++) {
            CP_WAIT(0);
            __syncthreads();
            if (s < 3)       load64(shKV[(s + 1) & 1], Kj + (size_t)(s + 1) * 64 * Hv);
            else             load64(shKV[0],           Vj);            // V(jb,0)
            CP_COMMIT();

            const float* kb = shKV[s & 1];
            wmma::fragment<wmma::accumulator, 16, 16, 8, float> accs[2];
            wmma::fill_fragment(accs[0], 0.0f);
            wmma::fill_fragment(accs[1], 0.0f);
#pragma unroll
            for (int k = 0; k < 16; k++) {
#pragma unroll
                for (int j = 0; j < 2; j++) {
                    wmma::fragment<wmma::matrix_b, 16, 16, 8, wmma::precision::tf32, wmma::col_major> bf;
                    wmma::load_matrix_sync(bf, kb + (wns * 32 + j * 16) * AST + k * 8, AST);
                    wmma::mma_sync(accs[j], qf[k], bf, accs[j]);
                }
            }
#pragma unroll
            for (int j = 0; j < 2; j++)
                wmma::store_matrix_sync(
                    shS + (wms * 16) * SST + s * 64 + wns * 32 + j * 16,
                    accs[j], SST, wmma::mem_row_major);
        }
        __syncthreads();   // S complete

        // ---- per-block softmax over 256 keys, no max shift ----
        {
            float* srow = shS + row * SST + part * 64;
            const bool diag = (jb == bi);
            const int cbase = part * 64;

            float sumv = 0.0f;
#pragma unroll 8
            for (int c = 0; c < 64; c++) {
                bool masked = diag && (cbase + c > qoff);
                float p = masked ? 0.0f : __expf(srow[c] * ATT_SCALE);
                srow[c] = p;
                sumv += p;
            }
            sumv += __shfl_xor_sync(0xffffffffu, sumv, 1);
            sumv += __shfl_xor_sync(0xffffffffu, sumv, 2);
            float inv = 1.0f / sumv;
#pragma unroll 8
            for (int c = 0; c < 64; c++) srow[c] = to_tf32(srow[c] * inv);
        }

        // ---- PV phase: 4 subtiles of 64 kv rows ----
#pragma unroll
        for (int v = 0; v < 4; v++) {
            CP_WAIT(0);
            __syncthreads();    // also orders softmax writes before PV reads
            if (v < 3)          load64(shKV[(v + 1) & 1], Vj + (size_t)(v + 1) * 64 * Hv);
            else if (jb < bi)   load64(shKV[0], Kj + (size_t)BSv * Hv);  // K(jb+1,0)
            CP_COMMIT();

            const float* vb = shKV[v & 1];
#pragma unroll
            for (int k = 0; k < 64; k += 8) {
                wmma::fragment<wmma::matrix_a, 16, 16, 8, wmma::precision::tf32, wmma::row_major> af[2];
#pragma unroll
                for (int i = 0; i < 2; i++)
                    wmma::load_matrix_sync(af[i], shS + (wmo * 32 + i * 16) * SST + v * 64 + k, SST);
#pragma unroll
                for (int j = 0; j < 2; j++) {
                    wmma::fragment<wmma::matrix_b, 16, 16, 8, wmma::precision::tf32, wmma::row_major> bf;
                    wmma::load_matrix_sync(bf, vb + k * AST + wno * 32 + j * 16, AST);
#pragma unroll
                    for (int i = 0; i < 2; i++)
                        wmma::mma_sync(acc_o[i][j], af[i], bf, acc_o[i][j]);
                }
            }
        }
    }

    // ---- epilogue ----
    const float invc = 1.0f / ((float)(bi + 1) + 1e-6f);
#pragma unroll
    for (int i = 0; i < 2; i++)
#pragma unroll
        for (int j = 0; j < 2; j++) {
#pragma unroll
            for (int t = 0; t < acc_o[i][j].num_elements; t++)
                acc_o[i][j].x[t] = to_tf32(acc_o[i][j].x[t] * invc);
            wmma::store_matrix_sync(
                g_o + ((size_t)(b * Sv + qbase + wmo * 32 + i * 16)) * Hv + h * HDv + wno * 32 + j * 16,
                acc_o[i][j], Hv, wmma::mem_row_major);
        }
}

// ===========================================================================
// launch
// ===========================================================================
extern "C" void kernel_launch(void* const* d_in, const int* in_sizes, int n_in,
                              void* d_out, int out_size)
{
    const float* X  = (const float*)d_in[0];
    const float* Wq = (const float*)d_in[1];
    const float* Wk = (const float*)d_in[2];
    const float* Wv = (const float*)d_in[3];
    const float* Wo = (const float*)d_in[4];
    float* out = (float*)d_out;

    float *q, *k, *v, *o, *xr, *wq, *wk, *wv, *wo;
    cudaGetSymbolAddress((void**)&q,  g_q);
    cudaGetSymbolAddress((void**)&k,  g_k);
    cudaGetSymbolAddress((void**)&v,  g_v);
    cudaGetSymbolAddress((void**)&o,  g_o);
    cudaGetSymbolAddress((void**)&xr, g_xr);
    cudaGetSymbolAddress((void**)&wq, g_wq);
    cudaGetSymbolAddress((void**)&wk, g_wk);
    cudaGetSymbolAddress((void**)&wv, g_wv);
    cudaGetSymbolAddress((void**)&wo, g_wo);

    const size_t attn_smem = (size_t)(3 * QT * AST + QT * SST) * sizeof(float);  // 167936

    cudaFuncSetAttribute(gemm_pipe, cudaFuncAttributeMaxDynamicSharedMemorySize, GEMM_SMEM);
    cudaFuncSetAttribute(attn_kernel, cudaFuncAttributeMaxDynamicSharedMemorySize, (int)attn_smem);

    // RNA-round all inputs to tf32 in one launch.
    round_all_k<<<(NX4 + 4 * NW4) / 256, 256>>>(
        (const float4*)X, (const float4*)Wq, (const float4*)Wk,
        (const float4*)Wv, (const float4*)Wo);

    dim3 gg(Hv / BN, Mtot / BM);     // (16, 16) = 256 CTAs
    gemm_pipe<<<gg, 256, GEMM_SMEM>>>(xr, wq, q, Mtot, Hv, Hv, 1);
    gemm_pipe<<<gg, 256, GEMM_SMEM>>>(xr, wk, k, Mtot, Hv, Hv, 1);
    gemm_pipe<<<gg, 256, GEMM_SMEM>>>(xr, wv, v, Mtot, Hv, Hv, 1);

    dim3 ag(Sv / QT, NHv, Bv);       // (32, 16, 2)
    attn_kernel<<<ag, 256, attn_smem>>>();

    gemm_pipe<<<gg, 256, GEMM_SMEM>>>(o, wo, out, Mtot, Hv, Hv, 0);
}

// round 11
// speedup vs baseline: 1.4852x; 1.4852x over previous
#include <cuda_runtime.h>
#include <mma.h>
#include <cstdint>
#include <cstddef>

using namespace nvcuda;

#define Bv   2
#define Sv   2048
#define Hv   2048
#define NHv  16
#define HDv  128
#define BSv  256
#define Mtot (Bv * Sv)
#define ATT_SCALE 0.08838834764831843f  // 1/sqrt(128)

// ---------------- scratch (__device__ globals, allocation-free rule) -------
__device__ float g_q[(size_t)Mtot * Hv];
__device__ float g_k[(size_t)Mtot * Hv];
__device__ float g_v[(size_t)Mtot * Hv];
__device__ float g_o[(size_t)Mtot * Hv];
__device__ float g_xr[(size_t)Mtot * Hv];
__device__ float g_wq[(size_t)Hv * Hv];
__device__ float g_wk[(size_t)Hv * Hv];
__device__ float g_wv[(size_t)Hv * Hv];
__device__ float g_wo[(size_t)Hv * Hv];

// ---------------- helpers ---------------------------------------------------
__device__ __forceinline__ float to_tf32(float x) {
    float y;
    asm("cvt.rna.tf32.f32 %0, %1;" : "=f"(y) : "f"(x));
    return y;
}

__device__ __forceinline__ uint32_t smem_u32(const void* p) {
    uint32_t a;
    asm("{ .reg .u64 t; cvta.to.shared.u64 t, %1; cvt.u32.u64 %0, t; }" : "=r"(a) : "l"(p));
    return a;
}

__device__ __forceinline__ void cp_async16(uint32_t saddr, const void* gptr) {
    asm volatile("cp.async.cg.shared.global [%0], [%1], 16;" :: "r"(saddr), "l"(gptr));
}
#define CP_COMMIT() asm volatile("cp.async.commit_group;")
#define CP_WAIT(n)  asm volatile("cp.async.wait_group %0;" :: "n"(n))

// ---------------- rounding pre-pass ----------------------------------------
__global__ void __launch_bounds__(256) round_tf32_k(
    const float4* __restrict__ s, float4* __restrict__ d, int n4)
{
    int i = blockIdx.x * 256 + threadIdx.x;
    if (i < n4) {
        float4 v = s[i];
        v.x = to_tf32(v.x); v.y = to_tf32(v.y);
        v.z = to_tf32(v.z); v.w = to_tf32(v.w);
        d[i] = v;
    }
}

// ===========================================================================
// Pipelined tf32 wmma GEMM — the 2810us-measured configuration:
// CTA tile 256x128x32, 8 warps (4x2) with 64x64 warp tiles, 4-stage cp.async,
// 1 CTA/SM. do_round=1 -> epilogue RNA-rounds C to tf32.
// ===========================================================================
#define BM 256
#define BN 128
#define BK 32
#define STR 36                       // 32 + 4 pad floats; 144B rows (16B-aligned)
#define NSTG 4
#define A_FLTS (BM * STR)            // 9216
#define B_FLTS (BN * STR)            // 4608
#define STAGE_FLTS (A_FLTS + B_FLTS) // 13824
#define GEMM_SMEM (NSTG * STAGE_FLTS * 4)   // 221184 B -> 1 CTA/SM

__device__ __forceinline__ void stage_load(
    float* stg, const float* __restrict__ Ag, const float* __restrict__ Bg,
    int K, int tid)
{
#pragma unroll
    for (int i = 0; i < 8; i++) {      // A: 256 rows x 8 x 16B
        int id = tid + i * 256;
        int r = id >> 3, c = id & 7;
        cp_async16(smem_u32(stg + r * STR + c * 4), Ag + (size_t)r * K + c * 4);
    }
#pragma unroll
    for (int i = 0; i < 4; i++) {      // B: 128 rows x 8 x 16B
        int id = tid + i * 256;
        int r = id >> 3, c = id & 7;
        cp_async16(smem_u32(stg + A_FLTS + r * STR + c * 4), Bg + (size_t)r * K + c * 4);
    }
}

__global__ void __launch_bounds__(256, 1) gemm_pipe(
    const float* __restrict__ A, const float* __restrict__ Bw,
    float* __restrict__ C, int M, int N, int K, int do_round)
{
    extern __shared__ __align__(16) float sm[];

    const int tid = threadIdx.x;
    const int wid = tid >> 5;
    const int m0 = blockIdx.y * BM;
    const int n0 = blockIdx.x * BN;
    const int wm = wid & 3;    // 4 warp rows x 64 m
    const int wn = wid >> 2;   // 2 warp cols x 64 n

    const float* Abase = A + (size_t)m0 * K;
    const float* Bbase = Bw + (size_t)n0 * K;
    const int KT = K / BK;

    wmma::fragment<wmma::accumulator, 16, 16, 8, float> acc[4][4];
#pragma unroll
    for (int i = 0; i < 4; i++)
#pragma unroll
        for (int j = 0; j < 4; j++) wmma::fill_fragment(acc[i][j], 0.0f);

    // prologue: stages 0..NSTG-2 <- k-tiles 0..NSTG-2
#pragma unroll
    for (int t = 0; t < NSTG - 1; t++) {
        stage_load(sm + t * STAGE_FLTS, Abase + t * BK, Bbase + t * BK, K, tid);
        CP_COMMIT();
    }

    for (int kt = 0; kt < KT; kt++) {
        CP_WAIT(NSTG - 2);          // k-tile kt resident
        __syncthreads();            // also fences reads of the stage refilled below

        int tn = kt + NSTG - 1;
        if (tn < KT)
            stage_load(sm + (tn % NSTG) * STAGE_FLTS, Abase + (size_t)tn * BK,
                       Bbase + (size_t)tn * BK, K, tid);
        CP_COMMIT();

        const float* sA = sm + (kt % NSTG) * STAGE_FLTS;
        const float* sB = sA + A_FLTS;

#pragma unroll
        for (int kk = 0; kk < 4; kk++) {
            wmma::fragment<wmma::matrix_a, 16, 16, 8, wmma::precision::tf32, wmma::row_major> af[4];
            wmma::fragment<wmma::matrix_b, 16, 16, 8, wmma::precision::tf32, wmma::col_major> bf[4];
#pragma unroll
            for (int i = 0; i < 4; i++)
                wmma::load_matrix_sync(af[i], sA + (wm * 64 + i * 16) * STR + kk * 8, STR);
#pragma unroll
            for (int j = 0; j < 4; j++)
                wmma::load_matrix_sync(bf[j], sB + (wn * 64 + j * 16) * STR + kk * 8, STR);
#pragma unroll
            for (int j = 0; j < 4; j++)
#pragma unroll
                for (int i = 0; i < 4; i++)
                    wmma::mma_sync(acc[i][j], af[i], bf[j], acc[i][j]);
        }
    }

#pragma unroll
    for (int i = 0; i < 4; i++)
#pragma unroll
        for (int j = 0; j < 4; j++) {
            if (do_round) {
#pragma unroll
                for (int t = 0; t < acc[i][j].num_elements; t++)
                    acc[i][j].x[t] = to_tf32(acc[i][j].x[t]);
            }
            wmma::store_matrix_sync(
                C + (size_t)(m0 + wm * 64 + i * 16) * N + n0 + wn * 64 + j * 16,
                acc[i][j], N, wmma::mem_row_major);
        }
}

// ===========================================================================
// Attention — the 2810us-measured structure; ONLY change: softmax drops the
// row-max pass (shift-invariant; scores*SCALE are O(+-6), exp is fp32-safe).
// K/V subtiles double-buffered via cp.async, one subtile ahead.
// ===========================================================================
#define QT  64
#define AST 132   // 128 + 4 pad
#define SST 260   // 256 + 4 pad

__global__ void __launch_bounds__(256) attn_kernel()
{
    extern __shared__ __align__(16) float sm[];
    float* shQ  = sm;                          // [64][AST]
    float* shKV[2] = { shQ + QT * AST, shQ + 2 * QT * AST };
    float* shS  = shQ + 3 * QT * AST;          // [64][SST]

    const int tid = threadIdx.x;
    const int wid = tid >> 5;
    const int qt = blockIdx.x;
    const int h  = blockIdx.y;
    const int b  = blockIdx.z;
    const int qbase = qt * QT;
    const int bi = qbase >> 8;

    const float* Qp    = g_q + ((size_t)b * Sv + qbase) * Hv + h * HDv;
    const float* Kbase = g_k + ((size_t)b * Sv) * Hv + h * HDv;
    const float* Vbase = g_v + ((size_t)b * Sv) * Hv + h * HDv;

    auto load64 = [&](float* dst, const float* src) {
#pragma unroll
        for (int i = 0; i < 8; i++) {
            int id = tid + i * 256;
            int r = id >> 5, c4 = id & 31;
            cp_async16(smem_u32(dst + r * AST + c4 * 4), src + (size_t)r * Hv + c4 * 4);
        }
    };

    load64(shQ, Qp);
    load64(shKV[0], Kbase);   // K(jb=0, sub=0)
    CP_COMMIT();

    wmma::fragment<wmma::accumulator, 16, 16, 8, float> acc_o[2][2];
#pragma unroll
    for (int i = 0; i < 2; i++)
#pragma unroll
        for (int j = 0; j < 2; j++) wmma::fill_fragment(acc_o[i][j], 0.0f);

    const int wms = wid & 3,  wns = wid >> 2;   // S phase: 16 rows x 32 cols
    const int wmo = wid & 1,  wno = wid >> 1;   // O phase: 32 rows x 32 cols

    const int row  = tid >> 2;
    const int part = tid & 3;
    const int qoff = (qbase & 255) + row;

    for (int jb = 0; jb <= bi; jb++) {
        const float* Kj = Kbase + (size_t)jb * BSv * Hv;
        const float* Vj = Vbase + (size_t)jb * BSv * Hv;

        // ---- S phase: 4 subtiles of 64 keys ----
#pragma unroll
        for (int s = 0; s < 4; s++) {
            CP_WAIT(0);
            __syncthreads();
            if (s < 3)       load64(shKV[(s + 1) & 1], Kj + (size_t)(s + 1) * 64 * Hv);
            else             load64(shKV[0],           Vj);            // V(jb,0)
            CP_COMMIT();

            const float* kb = shKV[s & 1];
            wmma::fragment<wmma::accumulator, 16, 16, 8, float> accs[2];
            wmma::fill_fragment(accs[0], 0.0f);
            wmma::fill_fragment(accs[1], 0.0f);
#pragma unroll
            for (int k = 0; k < HDv; k += 8) {
                wmma::fragment<wmma::matrix_a, 16, 16, 8, wmma::precision::tf32, wmma::row_major> af;
                wmma::load_matrix_sync(af, shQ + (wms * 16) * AST + k, AST);
#pragma unroll
                for (int j = 0; j < 2; j++) {
                    wmma::fragment<wmma::matrix_b, 16, 16, 8, wmma::precision::tf32, wmma::col_major> bf;
                    wmma::load_matrix_sync(bf, kb + (wns * 32 + j * 16) * AST + k, AST);
                    wmma::mma_sync(accs[j], af, bf, accs[j]);
                }
            }
#pragma unroll
            for (int j = 0; j < 2; j++)
                wmma::store_matrix_sync(
                    shS + (wms * 16) * SST + s * 64 + wns * 32 + j * 16,
                    accs[j], SST, wmma::mem_row_major);
        }
        __syncthreads();   // S complete

        // ---- per-block softmax over 256 keys, no max shift ----
        {
            float* srow = shS + row * SST + part * 64;
            const bool diag = (jb == bi);
            const int cbase = part * 64;

            float sumv = 0.0f;
#pragma unroll 8
            for (int c = 0; c < 64; c++) {
                bool masked = diag && (cbase + c > qoff);
                float p = masked ? 0.0f : __expf(srow[c] * ATT_SCALE);
                srow[c] = p;
                sumv += p;
            }
            sumv += __shfl_xor_sync(0xffffffffu, sumv, 1);
            sumv += __shfl_xor_sync(0xffffffffu, sumv, 2);
            float inv = 1.0f / sumv;
#pragma unroll 8
            for (int c = 0; c < 64; c++) srow[c] = to_tf32(srow[c] * inv);
        }

        // ---- PV phase: 4 subtiles of 64 kv rows ----
#pragma unroll
        for (int v = 0; v < 4; v++) {
            CP_WAIT(0);
            __syncthreads();    // also orders softmax writes before PV reads
            if (v < 3)          load64(shKV[(v + 1) & 1], Vj + (size_t)(v + 1) * 64 * Hv);
            else if (jb < bi)   load64(shKV[0], Kj + (size_t)BSv * Hv);  // K(jb+1,0)
            CP_COMMIT();

            const float* vb = shKV[v & 1];
#pragma unroll
            for (int k = 0; k < 64; k += 8) {
                wmma::fragment<wmma::matrix_a, 16, 16, 8, wmma::precision::tf32, wmma::row_major> af[2];
#pragma unroll
                for (int i = 0; i < 2; i++)
                    wmma::load_matrix_sync(af[i], shS + (wmo * 32 + i * 16) * SST + v * 64 + k, SST);
#pragma unroll
                for (int j = 0; j < 2; j++) {
                    wmma::fragment<wmma::matrix_b, 16, 16, 8, wmma::precision::tf32, wmma::row_major> bf;
                    wmma::load_matrix_sync(bf, vb + k * AST + wno * 32 + j * 16, AST);
#pragma unroll
                    for (int i = 0; i < 2; i++)
                        wmma::mma_sync(acc_o[i][j], af[i], bf, acc_o[i][j]);
                }
            }
        }
    }

    // ---- epilogue ----
    const float invc = 1.0f / ((float)(bi + 1) + 1e-6f);
#pragma unroll
    for (int i = 0; i < 2; i++)
#pragma unroll
        for (int j = 0; j < 2; j++) {
#pragma unroll
            for (int t = 0; t < acc_o[i][j].num_elements; t++)
                acc_o[i][j].x[t] = to_tf32(acc_o[i][j].x[t] * invc);
            wmma::store_matrix_sync(
                g_o + ((size_t)(b * Sv + qbase + wmo * 32 + i * 16)) * Hv + h * HDv + wno * 32 + j * 16,
                acc_o[i][j], Hv, wmma::mem_row_major);
        }
}

// ===========================================================================
// launch — identical structure to the 2810us run
// ===========================================================================
extern "C" void kernel_launch(void* const* d_in, const int* in_sizes, int n_in,
                              void* d_out, int out_size)
{
    const float* X  = (const float*)d_in[0];
    const float* Wq = (const float*)d_in[1];
    const float* Wk = (const float*)d_in[2];
    const float* Wv = (const float*)d_in[3];
    const float* Wo = (const float*)d_in[4];
    float* out = (float*)d_out;

    float *q, *k, *v, *o, *xr, *wq, *wk, *wv, *wo;
    cudaGetSymbolAddress((void**)&q,  g_q);
    cudaGetSymbolAddress((void**)&k,  g_k);
    cudaGetSymbolAddress((void**)&v,  g_v);
    cudaGetSymbolAddress((void**)&o,  g_o);
    cudaGetSymbolAddress((void**)&xr, g_xr);
    cudaGetSymbolAddress((void**)&wq, g_wq);
    cudaGetSymbolAddress((void**)&wk, g_wk);
    cudaGetSymbolAddress((void**)&wv, g_wv);
    cudaGetSymbolAddress((void**)&wo, g_wo);

    const size_t attn_smem = (size_t)(3 * QT * AST + QT * SST) * sizeof(float);  // 167936

    cudaFuncSetAttribute(gemm_pipe, cudaFuncAttributeMaxDynamicSharedMemorySize, GEMM_SMEM);
    cudaFuncSetAttribute(attn_kernel, cudaFuncAttributeMaxDynamicSharedMemorySize, (int)attn_smem);

    // RNA-round inputs to tf32 once; mma's tf32 truncation then becomes exact.
    const int nX4 = Mtot * Hv / 4;
    const int nW4 = Hv * Hv / 4;
    round_tf32_k<<<(nX4 + 255) / 256, 256>>>((const float4*)X,  (float4*)xr, nX4);
    round_tf32_k<<<(nW4 + 255) / 256, 256>>>((const float4*)Wq, (float4*)wq, nW4);
    round_tf32_k<<<(nW4 + 255) / 256, 256>>>((const float4*)Wk, (float4*)wk, nW4);
    round_tf32_k<<<(nW4 + 255) / 256, 256>>>((const float4*)Wv, (float4*)wv, nW4);
    round_tf32_k<<<(nW4 + 255) / 256, 256>>>((const float4*)Wo, (float4*)wo, nW4);

    dim3 gg(Hv / BN, Mtot / BM);     // (16, 16) = 256 CTAs
    gemm_pipe<<<gg, 256, GEMM_SMEM>>>(xr, wq, q, Mtot, Hv, Hv, 1);
    gemm_pipe<<<gg, 256, GEMM_SMEM>>>(xr, wk, k, Mtot, Hv, Hv, 1);
    gemm_pipe<<<gg, 256, GEMM_SMEM>>>(xr, wv, v, Mtot, Hv, Hv, 1);

    dim3 ag(Sv / QT, NHv, Bv);       // (32, 16, 2)
    attn_kernel<<<ag, 256, attn_smem>>>();

    gemm_pipe<<<gg, 256, GEMM_SMEM>>>(o, wo, out, Mtot, Hv, Hv, 0);
}

// round 12
// speedup vs baseline: 1.6684x; 1.1234x over previous
#include <cuda_runtime.h>
#include <mma.h>
#include <cstdint>
#include <cstddef>

using namespace nvcuda;

#define Bv   2
#define Sv   2048
#define Hv   2048
#define NHv  16
#define HDv  128
#define BSv  256
#define Mtot (Bv * Sv)
#define ATT_SCALE 0.08838834764831843f  // 1/sqrt(128)

// ---------------- scratch (__device__ globals, allocation-free rule) -------
__device__ float g_q[(size_t)Mtot * Hv];
__device__ float g_k[(size_t)Mtot * Hv];
__device__ float g_v[(size_t)Mtot * Hv];
__device__ float g_o[(size_t)Mtot * Hv];
__device__ float g_xr[(size_t)Mtot * Hv];
__device__ float g_wq[(size_t)Hv * Hv];
__device__ float g_wk[(size_t)Hv * Hv];
__device__ float g_wv[(size_t)Hv * Hv];
__device__ float g_wo[(size_t)Hv * Hv];

// ---------------- helpers ---------------------------------------------------
__device__ __forceinline__ float to_tf32(float x) {
    float y;
    asm("cvt.rna.tf32.f32 %0, %1;" : "=f"(y) : "f"(x));
    return y;
}

__device__ __forceinline__ uint32_t smem_u32(const void* p) {
    uint32_t a;
    asm("{ .reg .u64 t; cvta.to.shared.u64 t, %1; cvt.u32.u64 %0, t; }" : "=r"(a) : "l"(p));
    return a;
}

__device__ __forceinline__ void cp_async16(uint32_t saddr, const void* gptr) {
    asm volatile("cp.async.cg.shared.global [%0], [%1], 16;" :: "r"(saddr), "l"(gptr));
}
#define CP_COMMIT() asm volatile("cp.async.commit_group;")
#define CP_WAIT(n)  asm volatile("cp.async.wait_group %0;" :: "n"(n))
#define CP_WAIT_DYN(cond_one) do { if (cond_one) CP_WAIT(1); else CP_WAIT(0); } while (0)

// ---------------- rounding pre-pass ----------------------------------------
__global__ void __launch_bounds__(256) round_tf32_k(
    const float4* __restrict__ s, float4* __restrict__ d, int n4)
{
    int i = blockIdx.x * 256 + threadIdx.x;
    if (i < n4) {
        float4 v = s[i];
        v.x = to_tf32(v.x); v.y = to_tf32(v.y);
        v.z = to_tf32(v.z); v.w = to_tf32(v.w);
        d[i] = v;
    }
}

// ===========================================================================
// Pipelined tf32 wmma GEMM — R4 configuration (untouched, best measured):
// CTA tile 256x128x32, 8 warps (4x2) with 64x64 warp tiles, 4-stage cp.async.
// ===========================================================================
#define BM 256
#define BN 128
#define BK 32
#define STR 36
#define NSTG 4
#define A_FLTS (BM * STR)
#define B_FLTS (BN * STR)
#define STAGE_FLTS (A_FLTS + B_FLTS)
#define GEMM_SMEM (NSTG * STAGE_FLTS * 4)   // 221184 B -> 1 CTA/SM

__device__ __forceinline__ void stage_load(
    float* stg, const float* __restrict__ Ag, const float* __restrict__ Bg,
    int K, int tid)
{
#pragma unroll
    for (int i = 0; i < 8; i++) {
        int id = tid + i * 256;
        int r = id >> 3, c = id & 7;
        cp_async16(smem_u32(stg + r * STR + c * 4), Ag + (size_t)r * K + c * 4);
    }
#pragma unroll
    for (int i = 0; i < 4; i++) {
        int id = tid + i * 256;
        int r = id >> 3, c = id & 7;
        cp_async16(smem_u32(stg + A_FLTS + r * STR + c * 4), Bg + (size_t)r * K + c * 4);
    }
}

__global__ void __launch_bounds__(256, 1) gemm_pipe(
    const float* __restrict__ A, const float* __restrict__ Bw,
    float* __restrict__ C, int M, int N, int K, int do_round)
{
    extern __shared__ __align__(16) float sm[];

    const int tid = threadIdx.x;
    const int wid = tid >> 5;
    const int m0 = blockIdx.y * BM;
    const int n0 = blockIdx.x * BN;
    const int wm = wid & 3;
    const int wn = wid >> 2;

    const float* Abase = A + (size_t)m0 * K;
    const float* Bbase = Bw + (size_t)n0 * K;
    const int KT = K / BK;

    wmma::fragment<wmma::accumulator, 16, 16, 8, float> acc[4][4];
#pragma unroll
    for (int i = 0; i < 4; i++)
#pragma unroll
        for (int j = 0; j < 4; j++) wmma::fill_fragment(acc[i][j], 0.0f);

#pragma unroll
    for (int t = 0; t < NSTG - 1; t++) {
        stage_load(sm + t * STAGE_FLTS, Abase + t * BK, Bbase + t * BK, K, tid);
        CP_COMMIT();
    }

    for (int kt = 0; kt < KT; kt++) {
        CP_WAIT(NSTG - 2);
        __syncthreads();

        int tn = kt + NSTG - 1;
        if (tn < KT)
            stage_load(sm + (tn % NSTG) * STAGE_FLTS, Abase + (size_t)tn * BK,
                       Bbase + (size_t)tn * BK, K, tid);
        CP_COMMIT();

        const float* sA = sm + (kt % NSTG) * STAGE_FLTS;
        const float* sB = sA + A_FLTS;

#pragma unroll
        for (int kk = 0; kk < 4; kk++) {
            wmma::fragment<wmma::matrix_a, 16, 16, 8, wmma::precision::tf32, wmma::row_major> af[4];
            wmma::fragment<wmma::matrix_b, 16, 16, 8, wmma::precision::tf32, wmma::col_major> bf[4];
#pragma unroll
            for (int i = 0; i < 4; i++)
                wmma::load_matrix_sync(af[i], sA + (wm * 64 + i * 16) * STR + kk * 8, STR);
#pragma unroll
            for (int j = 0; j < 4; j++)
                wmma::load_matrix_sync(bf[j], sB + (wn * 64 + j * 16) * STR + kk * 8, STR);
#pragma unroll
            for (int j = 0; j < 4; j++)
#pragma unroll
                for (int i = 0; i < 4; i++)
                    wmma::mma_sync(acc[i][j], af[i], bf[j], acc[i][j]);
        }
    }

#pragma unroll
    for (int i = 0; i < 4; i++)
#pragma unroll
        for (int j = 0; j < 4; j++) {
            if (do_round) {
#pragma unroll
                for (int t = 0; t < acc[i][j].num_elements; t++)
                    acc[i][j].x[t] = to_tf32(acc[i][j].x[t]);
            }
            wmma::store_matrix_sync(
                C + (size_t)(m0 + wm * 64 + i * 16) * N + n0 + wn * 64 + j * 16,
                acc[i][j], N, wmma::mem_row_major);
        }
}

// ===========================================================================
// Attention, transposed-S formulation:
//   S^T(256 keys x 64 q) = K @ Q^T   in 128-key supersteps, 32x32 warp tiles
//   per-block softmax over S^T columns (no-max; shift-invariant)
//   O^T(128 d x 64 q) += V^T @ P^T   in 64-key subtiles, 32x32 warp tiles
//   epilogue stores O^T col-major == O row-major.
// 3 KV buffers; cp.async slotted so only K4 is exposed per block.
// ===========================================================================
#define QT  64
#define AST 132   // 128 + 4 pad floats (16B-aligned rows)
#define STT 68    // 64 + 4 pad floats (S^T row = 64 queries)

#define SM_Q   0
#define SM_KV  (QT * AST)                    // 3 x [64][AST]
#define KVSZ   (64 * AST)
#define SM_ST  (SM_KV + 3 * KVSZ)            // [256][STT]
#define SM_RED (SM_ST + 256 * STT)           // [256]
#define SM_INV (SM_RED + 256)                // [64]
#define ATTN_SMEM ((SM_INV + 64) * 4)        // 206080 B

__global__ void __launch_bounds__(256) attn_kernel()
{
    extern __shared__ __align__(16) float sm[];
    float* shQ  = sm + SM_Q;
    float* L0   = sm + SM_KV;
    float* L1   = L0 + KVSZ;
    float* L2   = L1 + KVSZ;
    float* shS  = sm + SM_ST;
    float* shRed = sm + SM_RED;
    float* shInv = sm + SM_INV;

    const int tid = threadIdx.x;
    const int wid = tid >> 5;
    const int qt = gridDim.x - 1 - blockIdx.x;   // expensive tiles first
    const int h  = blockIdx.y;
    const int b  = blockIdx.z;
    const int qbase = qt * QT;
    const int bi = qbase >> 8;

    const float* Qp    = g_q + ((size_t)b * Sv + qbase) * Hv + h * HDv;
    const float* Kbase = g_k + ((size_t)b * Sv) * Hv + h * HDv;
    const float* Vbase = g_v + ((size_t)b * Sv) * Hv + h * HDv;

    auto load64 = [&](float* dst, const float* src) {
#pragma unroll
        for (int i = 0; i < 8; i++) {
            int id = tid + i * 256;
            int r = id >> 5, c4 = id & 31;
            cp_async16(smem_u32(dst + r * AST + c4 * 4), src + (size_t)r * Hv + c4 * 4);
        }
    };

    const int wm = wid >> 1;   // 0..3
    const int wn = wid & 1;    // 0..1

    // softmax mapping: conflict-free columns of S^T
    const int sq = tid & 63;         // query
    const int sp = tid >> 6;         // key quarter (0..3)
    const int qoff = (qbase & 255) + sq;

    // accumulators: O^T, warp tile 32 dims x 32 queries
    wmma::fragment<wmma::accumulator, 16, 16, 8, float> acc_o[2][2];
#pragma unroll
    for (int i = 0; i < 2; i++)
#pragma unroll
        for (int j = 0; j < 2; j++) wmma::fill_fragment(acc_o[i][j], 0.0f);

    // prologue loads: Q, K1->L0, K2->L1
    load64(shQ, Qp);           CP_COMMIT();
    load64(L0, Kbase);         CP_COMMIT();
    load64(L1, Kbase + (size_t)64 * Hv);  CP_COMMIT();

    // S^T superstep: keys in (pa: rows 0-63, pb: rows 64-127), output rows ss*128..
    auto st_compute = [&](const float* pa, const float* pb, int ss) {
        const float* abase = ((wm < 2) ? pa : pb) + ((wm & 1) * 32) * AST;
        wmma::fragment<wmma::accumulator, 16, 16, 8, float> accs[2][2];
#pragma unroll
        for (int i = 0; i < 2; i++)
#pragma unroll
            for (int j = 0; j < 2; j++) wmma::fill_fragment(accs[i][j], 0.0f);
#pragma unroll
        for (int kk = 0; kk < 16; kk++) {
            wmma::fragment<wmma::matrix_a, 16, 16, 8, wmma::precision::tf32, wmma::row_major> af[2];
            wmma::fragment<wmma::matrix_b, 16, 16, 8, wmma::precision::tf32, wmma::col_major> bf[2];
#pragma unroll
            for (int i = 0; i < 2; i++)
                wmma::load_matrix_sync(af[i], abase + (i * 16) * AST + kk * 8, AST);
#pragma unroll
            for (int j = 0; j < 2; j++)
                wmma::load_matrix_sync(bf[j], shQ + (wn * 32 + j * 16) * AST + kk * 8, AST);
#pragma unroll
            for (int i = 0; i < 2; i++)
#pragma unroll
                for (int j = 0; j < 2; j++)
                    wmma::mma_sync(accs[i][j], af[i], bf[j], accs[i][j]);
        }
#pragma unroll
        for (int i = 0; i < 2; i++)
#pragma unroll
            for (int j = 0; j < 2; j++)
                wmma::store_matrix_sync(
                    shS + (ss * 128 + wm * 32 + i * 16) * STT + wn * 32 + j * 16,
                    accs[i][j], STT, wmma::mem_row_major);
    };

    // PV subtile: O^T += V^T(chunk) @ P^T(chunk); vb holds 64 kv rows, keys v*64..
    auto pv_compute = [&](const float* vb, int v) {
#pragma unroll
        for (int kk = 0; kk < 8; kk++) {
            wmma::fragment<wmma::matrix_a, 16, 16, 8, wmma::precision::tf32, wmma::col_major> af[2];
            wmma::fragment<wmma::matrix_b, 16, 16, 8, wmma::precision::tf32, wmma::row_major> bf[2];
#pragma unroll
            for (int i = 0; i < 2; i++)
                wmma::load_matrix_sync(af[i], vb + (kk * 8) * AST + wm * 32 + i * 16, AST);
#pragma unroll
            for (int j = 0; j < 2; j++)
                wmma::load_matrix_sync(bf[j], shS + (v * 64 + kk * 8) * STT + wn * 32 + j * 16, STT);
#pragma unroll
            for (int i = 0; i < 2; i++)
#pragma unroll
                for (int j = 0; j < 2; j++)
                    wmma::mma_sync(acc_o[i][j], af[i], bf[j], acc_o[i][j]);
        }
    };

    for (int jb = 0; jb <= bi; jb++) {
        const float* Kj = Kbase + (size_t)jb * BSv * Hv;
        const float* Vj = Vbase + (size_t)jb * BSv * Hv;
        const bool more = (jb < bi);

        // Phase A: ST1 on (L0, L1); prefetch K3->L2
        CP_WAIT(0);
        __syncthreads();
        load64(L2, Kj + (size_t)128 * Hv);  CP_COMMIT();
        st_compute(L0, L1, 0);

        // Phase B: ST2 on (L2, L0); K4->L0 (exposed), V1->L1 (hidden)
        __syncthreads();
        load64(L0, Kj + (size_t)192 * Hv);  CP_COMMIT();
        load64(L1, Vj);                     CP_COMMIT();
        CP_WAIT(1);                          // K3, K4 done; V1 pending
        __syncthreads();
        st_compute(L2, L0, 1);

        // Phase C: softmax; V2->L2, V3->L0 (hidden)
        __syncthreads();
        load64(L2, Vj + (size_t)64 * Hv);   CP_COMMIT();
        load64(L0, Vj + (size_t)128 * Hv);  CP_COMMIT();
        {
            const bool diag = (jb == bi);
            float sumv = 0.0f;
#pragma unroll 8
            for (int c = 0; c < 64; c++) {
                int key = sp * 64 + c;
                float* addr = shS + key * STT + sq;
                bool masked = diag && (key > qoff);
                float p = masked ? 0.0f : __expf(*addr * ATT_SCALE);
                *addr = p;
                sumv += p;
            }
            shRed[sp * 64 + sq] = sumv;
            __syncthreads();
            if (tid < 64)
                shInv[tid] = 1.0f / (shRed[tid] + shRed[64 + tid] +
                                     shRed[128 + tid] + shRed[192 + tid]);
            __syncthreads();
            float inv = shInv[sq];
#pragma unroll 8
            for (int c = 0; c < 64; c++) {
                float* addr = shS + (sp * 64 + c) * STT + sq;
                *addr = to_tf32(*addr * inv);
            }
        }

        // Phase D: PV1 on L1 (keys 0-63)
        CP_WAIT(2);                          // V1 done; V2,V3 pending
        __syncthreads();
        pv_compute(L1, 0);

        // Phase E: PV2 on L2 (keys 64-127); nK2->L1
        CP_WAIT(1);                          // V2 done; V3 pending
        __syncthreads();
        if (more) { load64(L1, Kj + (size_t)(BSv + 64) * Hv); CP_COMMIT(); }
        pv_compute(L2, 1);

        // Phase F: PV3 on L0 (keys 128-191); V4->L2
        CP_WAIT_DYN(more);                   // V3 done; (nK2) pending
        __syncthreads();
        load64(L2, Vj + (size_t)192 * Hv);  CP_COMMIT();
        pv_compute(L0, 2);

        // Phase G: PV4 on L2 (keys 192-255); nK1->L0
        CP_WAIT(0);                          // drains (nK2), V4
        __syncthreads();
        if (more) { load64(L0, Kj + (size_t)BSv * Hv); CP_COMMIT(); }
        pv_compute(L2, 3);
    }

    // ---- epilogue: scale, tf32-round, store O^T col-major (== O row-major) ----
    const float invc = 1.0f / ((float)(bi + 1) + 1e-6f);
#pragma unroll
    for (int i = 0; i < 2; i++)
#pragma unroll
        for (int j = 0; j < 2; j++) {
#pragma unroll
            for (int t = 0; t < acc_o[i][j].num_elements; t++)
                acc_o[i][j].x[t] = to_tf32(acc_o[i][j].x[t] * invc);
            wmma::store_matrix_sync(
                g_o + ((size_t)(b * Sv + qbase + wn * 32 + j * 16)) * Hv
                    + h * HDv + wm * 32 + i * 16,
                acc_o[i][j], Hv, wmma::mem_col_major);
        }
}

// ===========================================================================
// launch — R4 structure (separate launches)
// ===========================================================================
extern "C" void kernel_launch(void* const* d_in, const int* in_sizes, int n_in,
                              void* d_out, int out_size)
{
    const float* X  = (const float*)d_in[0];
    const float* Wq = (const float*)d_in[1];
    const float* Wk = (const float*)d_in[2];
    const float* Wv = (const float*)d_in[3];
    const float* Wo = (const float*)d_in[4];
    float* out = (float*)d_out;

    float *q, *k, *v, *o, *xr, *wq, *wk, *wv, *wo;
    cudaGetSymbolAddress((void**)&q,  g_q);
    cudaGetSymbolAddress((void**)&k,  g_k);
    cudaGetSymbolAddress((void**)&v,  g_v);
    cudaGetSymbolAddress((void**)&o,  g_o);
    cudaGetSymbolAddress((void**)&xr, g_xr);
    cudaGetSymbolAddress((void**)&wq, g_wq);
    cudaGetSymbolAddress((void**)&wk, g_wk);
    cudaGetSymbolAddress((void**)&wv, g_wv);
    cudaGetSymbolAddress((void**)&wo, g_wo);

    cudaFuncSetAttribute(gemm_pipe, cudaFuncAttributeMaxDynamicSharedMemorySize, GEMM_SMEM);
    cudaFuncSetAttribute(attn_kernel, cudaFuncAttributeMaxDynamicSharedMemorySize, ATTN_SMEM);

    const int nX4 = Mtot * Hv / 4;
    const int nW4 = Hv * Hv / 4;
    round_tf32_k<<<(nX4 + 255) / 256, 256>>>((const float4*)X,  (float4*)xr, nX4);
    round_tf32_k<<<(nW4 + 255) / 256, 256>>>((const float4*)Wq, (float4*)wq, nW4);
    round_tf32_k<<<(nW4 + 255) / 256, 256>>>((const float4*)Wk, (float4*)wk, nW4);
    round_tf32_k<<<(nW4 + 255) / 256, 256>>>((const float4*)Wv, (float4*)wv, nW4);
    round_tf32_k<<<(nW4 + 255) / 256, 256>>>((const float4*)Wo, (float4*)wo, nW4);

    dim3 gg(Hv / BN, Mtot / BM);     // (16, 16)
    gemm_pipe<<<gg, 256, GEMM_SMEM>>>(xr, wq, q, Mtot, Hv, Hv, 1);
    gemm_pipe<<<gg, 256, GEMM_SMEM>>>(xr, wk, k, Mtot, Hv, Hv, 1);
    gemm_pipe<<<gg, 256, GEMM_SMEM>>>(xr, wv, v, Mtot, Hv, Hv, 1);

    dim3 ag(Sv / QT, NHv, Bv);       // (32, 16, 2)
    attn_kernel<<<ag, 256, ATTN_SMEM>>>();

    gemm_pipe<<<gg, 256, GEMM_SMEM>>>(o, wo, out, Mtot, Hv, Hv, 0);
}